// round 16
// baseline (speedup 1.0000x reference)
#include <cuda_runtime.h>
#include <cuda_fp16.h>
#include <cstdint>
#include <math.h>

// ---------------- problem constants ----------------
#define Bsz   1024
#define Tlen  80
#define Dd    512
#define Cc    78
#define Mrows (Bsz*Tlen)          // 81920
#define BLANKI 77
#define PRED  30
#define LOGITS_ELEMS ((size_t)Mrows * Cc)

// ---------------- tiling (R13-proven shape) ----------------
#define BK    32                  // K per chunk (2 mma k-steps)
#define NCH   (Dd/BK)             // 16 chunks
#define AROW  40                  // fp16 row stride (32 data + 8 pad; 80B, 16B-aligned)
#define BROW  40
#define APL   (128*AROW*2)        // A plane bytes = 10240
#define BPL   (80*BROW*2)         // B plane bytes = 6400
#define BOFF  (2*APL)             // 20480
#define STAGE (BOFF + 2*BPL)      // 33280
#define SMEM_BYTES (2*STAGE)      // 66560 (>= 128*84*4 = 43008 epilogue bytes); 2 CTAs/SM
#define LP    84                  // epilogue logits row stride (floats)

// ---------------- device scratch (static, no runtime alloc) ----------------
__device__ int    g_best[Mrows];
__device__ __half g_Ws[2][80][Dd];   // W^T fp16 limbs: [limb][n][k]

// ---------------- helpers ----------------
// paired fp16 2-limb split: (x,y) -> 2 packed half2 limbs
__device__ __forceinline__ void split2x2(float x, float y,
                                         uint32_t& p0, uint32_t& p1) {
    __half2 h0 = __float22half2_rn(make_float2(x, y));
    float2 f0 = __half22float2(h0);
    __half2 h1 = __float22half2_rn(make_float2(x - f0.x, y - f0.y));
    p0 = *reinterpret_cast<uint32_t*>(&h0);
    p1 = *reinterpret_cast<uint32_t*>(&h1);
}

__device__ __forceinline__ void mma16816(float c[4], const uint32_t a[4],
                                         const uint32_t b[2]) {
    asm volatile(
        "mma.sync.aligned.m16n8k16.row.col.f32.f16.f16.f32 "
        "{%0,%1,%2,%3}, {%4,%5,%6,%7}, {%8,%9}, {%0,%1,%2,%3};"
        : "+f"(c[0]), "+f"(c[1]), "+f"(c[2]), "+f"(c[3])
        : "r"(a[0]), "r"(a[1]), "r"(a[2]), "r"(a[3]), "r"(b[0]), "r"(b[1]));
}

#define LDMX4(r, addr) \
    asm volatile("ldmatrix.sync.aligned.m8n8.x4.shared.b16 {%0,%1,%2,%3}, [%4];" \
        : "=r"((r)[0]), "=r"((r)[1]), "=r"((r)[2]), "=r"((r)[3]) : "r"(addr))
#define LDMX4P(r0, r1, addr) \
    asm volatile("ldmatrix.sync.aligned.m8n8.x4.shared.b16 {%0,%1,%2,%3}, [%4];" \
        : "=r"((r0)[0]), "=r"((r0)[1]), "=r"((r1)[0]), "=r"((r1)[1]) : "r"(addr))
#define LDMX2(r, addr) \
    asm volatile("ldmatrix.sync.aligned.m8n8.x2.shared.b16 {%0,%1}, [%2];" \
        : "=r"((r)[0]), "=r"((r)[1]) : "r"(addr))

__device__ __forceinline__ void cp_async16(uint32_t dst_smem, const void* src) {
    asm volatile("cp.async.cg.shared.global [%0], [%1], 16;" :: "r"(dst_smem), "l"(src));
}
#define CP_COMMIT() asm volatile("cp.async.commit_group;" ::: "memory")
#define CP_WAIT0()  asm volatile("cp.async.wait_group 0;" ::: "memory")

// ---------------- W prep: coalesced smem-transpose + 2-way fp16 split ----------------
// grid 8 x 256: each block handles 64 k-rows of W [512][78].
__global__ void prep_w(const float* __restrict__ Wm) {
    __shared__ float ws[64][80];
    const int t  = threadIdx.x;
    const int kb = blockIdx.x * 64;

    // coalesced load: consecutive threads read consecutive Wm elements
    for (int idx = t; idx < 64 * Cc; idx += 256) {
        const int kk = idx / Cc, n = idx - kk * Cc;
        ws[kk][n] = Wm[(size_t)(kb + kk) * Cc + n];
    }
    for (int idx = t; idx < 64 * 2; idx += 256)
        ws[idx >> 1][Cc + (idx & 1)] = 0.0f;
    __syncthreads();

    // coalesced writes along k for both limb planes
    for (int idx = t; idx < 80 * 64; idx += 256) {
        const int n = idx / 64, kk = idx - n * 64;
        const float v = ws[kk][n];
        const __half h0 = __float2half_rn(v);
        g_Ws[0][n][kb + kk] = h0;
        g_Ws[1][n][kb + kk] = __float2half_rn(v - __half2float(h0));
    }
}

// ---------------- fused mma GEMM + softmax + argmax ----------------
// CTA tile 128x80, 8 warps as (wm 0..3) x (wn 0..1): warp tile 32x40.
// Per k16-step: 3 limb passes {a0b0, a1b0, a0b1} (a1b1 ~2^-22, dropped).
__global__ __launch_bounds__(256, 2)
void gemm_mma_kernel(const float* __restrict__ feat,
                     const float* __restrict__ bias,
                     float* __restrict__ out)
{
    extern __shared__ char dsm[];
    __shared__ float bias_s[80];
    __shared__ float rinv_s[128];

    const int t    = threadIdx.x;
    const int lane = t & 31;
    const int wid  = t >> 5;
    const int wm   = wid & 3;
    const int wn   = wid >> 2;
    const int gID  = lane >> 2;
    const int tid4 = lane & 3;
    const int m0   = blockIdx.x * 128;
    const uint32_t dsmu = (uint32_t)__cvta_generic_to_shared(dsm);

    if (t < 80) bias_s[t] = (t < Cc) ? bias[t] : 0.0f;

    // ldmatrix per-lane address offsets (within plane)
    const uint32_t aoff0 = (uint32_t)((wm * 32 + (lane & 15)) * (AROW * 2) + (lane >> 4) * 16);
    const uint32_t aoff1 = aoff0 + 16 * (AROW * 2);
    const uint32_t boff0 = (uint32_t)((wn * 40 + (lane >> 4) * 8 + (lane & 7)) * (BROW * 2)
                                      + ((lane >> 3) & 1) * 16);
    const uint32_t boff2 = boff0 + 16 * (BROW * 2);
    const uint32_t boff4 = (uint32_t)((wn * 40 + 32 + (lane & 7)) * (BROW * 2)
                                      + ((lane >> 3) & 1) * 16);

    float acc[2][5][4];
#pragma unroll
    for (int i = 0; i < 2; i++)
#pragma unroll
        for (int j = 0; j < 5; j++)
#pragma unroll
            for (int q = 0; q < 4; q++) acc[i][j][q] = 0.0f;

    const float* featb = feat + (size_t)m0 * Dd;

    // ---- A store: split fp32 float4 -> 2 fp16 planes (one STS.64 per plane) ----
    auto storeA = [&](char* aB, int fidx, float4 v) {
        const int r = fidx >> 3, q = fidx & 7;       // 8 float4 per 32-float row
        const int off = r * (AROW * 2) + q * 8;
        uint2 u0, u1;
        split2x2(v.x, v.y, u0.x, u1.x);
        split2x2(v.z, v.w, u0.y, u1.y);
        *(uint2*)(aB + 0 * APL + off) = u0;
        *(uint2*)(aB + 1 * APL + off) = u1;
    };

    // ---- B load: 640 x 16B per chunk via cp.async (2 planes) ----
    auto loadB = [&](uint32_t bBu, int kb) {
#pragma unroll
        for (int i = 0; i < 3; i++) {
            const int idx = t + 256 * i;            // 0..767, use 0..639
            if (idx < 640) {
                const int p = idx / 320, rem = idx - p * 320;
                const int n = rem >> 2, q = rem & 3;
                cp_async16(bBu + p * BPL + n * (BROW * 2) + q * 16,
                           &g_Ws[p][n][kb + q * 8]);
            }
        }
    };

    // ---- prologue: chunk 0 ----
    {
        loadB(dsmu + BOFF, 0);
        CP_COMMIT();
#pragma unroll
        for (int i = 0; i < 4; i++) {
            const int fidx = t + 256 * i;           // 0..1023
            const int r = fidx >> 3, q = fidx & 7;
            float4 v = *reinterpret_cast<const float4*>(featb + (size_t)r * Dd + q * 4);
            storeA(dsm, fidx, v);
        }
        CP_WAIT0();
    }
    __syncthreads();

    // ---- main loop: 16 chunks ----
    for (int ch = 0; ch < NCH; ++ch) {
        const int s = ch & 1;
        const uint32_t aBu = dsmu + s * STAGE;
        const uint32_t bBu = aBu + BOFF;

        float4 pf[4];
        if (ch < NCH - 1) {
            const int kb = (ch + 1) * BK;
#pragma unroll
            for (int i = 0; i < 4; i++) {
                const int fidx = t + 256 * i;
                const int r = fidx >> 3, q = fidx & 7;
                pf[i] = *reinterpret_cast<const float4*>(featb + (size_t)r * Dd + kb + q * 4);
            }
            loadB(dsmu + (s ^ 1) * STAGE + BOFF, kb);
            CP_COMMIT();
        }

        // ---- 2 k-steps of 3-pass fp16 limb mma (ldmatrix fragments) ----
#pragma unroll
        for (int k0 = 0; k0 < 2; k0++) {
            const uint32_t kb2 = k0 * 32;           // 16 fp16 = 32 bytes
            uint32_t afr[2][2][4];
#pragma unroll
            for (int ai = 0; ai < 2; ai++) {
                LDMX4(afr[ai][0], aBu + ai * APL + aoff0 + kb2);
                LDMX4(afr[ai][1], aBu + ai * APL + aoff1 + kb2);
            }
#pragma unroll
            for (int bj = 0; bj < 2; bj++) {
                uint32_t b[5][2];
                LDMX4P(b[0], b[1], bBu + bj * BPL + boff0 + kb2);
                LDMX4P(b[2], b[3], bBu + bj * BPL + boff2 + kb2);
                LDMX2(b[4],        bBu + bj * BPL + boff4 + kb2);
#pragma unroll
                for (int ai = 0; ai <= 1 - bj; ai++)
#pragma unroll
                    for (int i = 0; i < 2; i++)
#pragma unroll
                        for (int j = 0; j < 5; j++)
                            mma16816(acc[i][j], afr[ai][i], b[j]);
            }
        }

        if (ch < NCH - 1) {
            char* aN = dsm + (s ^ 1) * STAGE;
#pragma unroll
            for (int i = 0; i < 4; i++) storeA(aN, t + 256 * i, pf[i]);
            CP_WAIT0();
        }
        __syncthreads();
    }

    // ---- stage logits (+bias) to smem ----
    float* L = (float*)dsm;
#pragma unroll
    for (int i = 0; i < 2; i++)
#pragma unroll
        for (int j = 0; j < 5; j++) {
            const int r0 = wm * 32 + i * 16 + gID;
            const int c0 = wn * 40 + j * 8 + tid4 * 2;
            L[r0 * LP + c0]           = acc[i][j][0] + bias_s[c0];
            L[r0 * LP + c0 + 1]       = acc[i][j][1] + bias_s[c0 + 1];
            L[(r0 + 8) * LP + c0]     = acc[i][j][2] + bias_s[c0];
            L[(r0 + 8) * LP + c0 + 1] = acc[i][j][3] + bias_s[c0 + 1];
        }
    __syncthreads();

    // ---- softmax + argmax: 2 threads per row (39 cols each) ----
    {
        const int r = t >> 1, h = t & 1;
        const int cb = h * 39;
        float mx = -1e30f; int am = 127;
        for (int c = 0; c < 39; c++) {
            float v = L[r * LP + cb + c];
            if (v > mx) { mx = v; am = cb + c; }
        }
        float omx = __shfl_xor_sync(0xFFFFFFFFu, mx, 1);
        int   oam = __shfl_xor_sync(0xFFFFFFFFu, am, 1);
        if (omx > mx || (omx == mx && oam < am)) { mx = omx; am = oam; }
        float ssum = 0.0f;
        for (int c = 0; c < 39; c++) {
            float e = __expf(L[r * LP + cb + c] - mx);
            L[r * LP + cb + c] = e;
            ssum += e;
        }
        ssum += __shfl_xor_sync(0xFFFFFFFFu, ssum, 1);
        if (h == 0) {
            rinv_s[r] = __frcp_rn(ssum);
            g_best[m0 + r] = am;
        }
    }
    __syncthreads();

    // ---- coalesced softmax prob writes ----
    for (int idx = t; idx < 128 * Cc; idx += 256) {
        const int r = idx / Cc, c = idx - r * Cc;
        out[(size_t)(m0 + r) * Cc + c] = L[r * LP + c] * rinv_s[r];
    }
}

// ---------------- CTC greedy collapse (warp-ballot, proven) ----------------
__global__ __launch_bounds__(256)
void decode_kernel(float* __restrict__ out, size_t out_elems)
{
    const int warp = (blockIdx.x * blockDim.x + threadIdx.x) >> 5;
    const int lane = threadIdx.x & 31;
    if (warp >= Bsz) return;

    size_t obase = LOGITS_ELEMS + (size_t)warp * PRED;
    if (obase + PRED > out_elems) return;
    float* lab = out + obase;

    if (lane < PRED) lab[lane] = -1.0f;
    __syncwarp();

    const int* row = g_best + (size_t)warp * Tlen;
    int prefix = 0;
    int carry  = -1;
#pragma unroll
    for (int seg = 0; seg < 3; seg++) {
        const int idx = seg * 32 + lane;
        const bool valid = (idx < Tlen);
        int v = valid ? row[idx] : BLANKI;
        int prev = __shfl_up_sync(0xFFFFFFFFu, v, 1);
        if (lane == 0) prev = carry;
        const bool keep = valid && (v != BLANKI) && (v != prev);
        const unsigned mask = __ballot_sync(0xFFFFFFFFu, keep);
        const int pos = prefix + __popc(mask & ((1u << lane) - 1u));
        if (keep && pos < PRED) lab[pos] = (float)v;
        prefix += __popc(mask);
        carry = __shfl_sync(0xFFFFFFFFu, v, 31);
    }
}

// ---------------- launch ----------------
extern "C" void kernel_launch(void* const* d_in, const int* in_sizes, int n_in,
                              void* d_out, int out_size)
{
    const float* feat = (const float*)d_in[0];  // [1024,80,512]
    const float* Wm   = (const float*)d_in[1];  // [512,78]
    const float* bias = (const float*)d_in[2];  // [78]
    float* out = (float*)d_out;

    cudaFuncSetAttribute(gemm_mma_kernel,
                         cudaFuncAttributeMaxDynamicSharedMemorySize, SMEM_BYTES);

    prep_w<<<8, 256>>>(Wm);
    gemm_mma_kernel<<<Mrows / 128, 256, SMEM_BYTES>>>(feat, bias, out);
    decode_kernel<<<(Bsz * 32) / 256, 256>>>(out, (size_t)out_size);
}

// round 17
// speedup vs baseline: 1.1184x; 1.1184x over previous
#include <cuda_runtime.h>
#include <cuda_fp16.h>
#include <cstdint>
#include <math.h>

// ---------------- problem constants ----------------
#define Bsz   1024
#define Tlen  80
#define Dd    512
#define Cc    78
#define Mrows (Bsz*Tlen)          // 81920
#define BLANKI 77
#define PRED  30
#define LOGITS_ELEMS ((size_t)Mrows * Cc)

// ---------------- tiling (R13-proven shape) ----------------
#define BK    32                  // K per chunk (2 mma k-steps)
#define NCH   (Dd/BK)             // 16 chunks
#define AROW  40                  // fp16 row stride (32 data + 8 pad; 80B, 16B-aligned)
#define BROW  40
#define APL   (128*AROW*2)        // A plane bytes = 10240
#define BPL   (80*BROW*2)         // B plane bytes = 6400
#define BOFF  (2*APL)             // 20480
#define STAGE (BOFF + 2*BPL)      // 33280
#define SMEM_BYTES (2*STAGE)      // 66560 (>= 128*84*4 = 43008 epilogue bytes); 2 CTAs/SM
#define LP    84                  // epilogue logits row stride (floats)

// ---------------- device scratch (static, zero-init, no runtime alloc) ----------------
__device__ int    g_best[Mrows];
__device__ int    g_cnt[Bsz];        // per-batch completed-row counters (reset by decoder)
__device__ __half g_Ws[2][80][Dd];   // W^T fp16 limbs: [limb][n][k]; pad rows stay zero

// ---------------- helpers ----------------
// paired fp16 2-limb split: (x,y) -> 2 packed half2 limbs
__device__ __forceinline__ void split2x2(float x, float y,
                                         uint32_t& p0, uint32_t& p1) {
    __half2 h0 = __float22half2_rn(make_float2(x, y));
    float2 f0 = __half22float2(h0);
    __half2 h1 = __float22half2_rn(make_float2(x - f0.x, y - f0.y));
    p0 = *reinterpret_cast<uint32_t*>(&h0);
    p1 = *reinterpret_cast<uint32_t*>(&h1);
}

__device__ __forceinline__ void mma16816(float c[4], const uint32_t a[4],
                                         const uint32_t b[2]) {
    asm volatile(
        "mma.sync.aligned.m16n8k16.row.col.f32.f16.f16.f32 "
        "{%0,%1,%2,%3}, {%4,%5,%6,%7}, {%8,%9}, {%0,%1,%2,%3};"
        : "+f"(c[0]), "+f"(c[1]), "+f"(c[2]), "+f"(c[3])
        : "r"(a[0]), "r"(a[1]), "r"(a[2]), "r"(a[3]), "r"(b[0]), "r"(b[1]));
}

#define LDMX4(r, addr) \
    asm volatile("ldmatrix.sync.aligned.m8n8.x4.shared.b16 {%0,%1,%2,%3}, [%4];" \
        : "=r"((r)[0]), "=r"((r)[1]), "=r"((r)[2]), "=r"((r)[3]) : "r"(addr))
#define LDMX4P(r0, r1, addr) \
    asm volatile("ldmatrix.sync.aligned.m8n8.x4.shared.b16 {%0,%1,%2,%3}, [%4];" \
        : "=r"((r0)[0]), "=r"((r0)[1]), "=r"((r1)[0]), "=r"((r1)[1]) : "r"(addr))
#define LDMX2(r, addr) \
    asm volatile("ldmatrix.sync.aligned.m8n8.x2.shared.b16 {%0,%1}, [%2];" \
        : "=r"((r)[0]), "=r"((r)[1]) : "r"(addr))

__device__ __forceinline__ void cp_async16(uint32_t dst_smem, const void* src) {
    asm volatile("cp.async.cg.shared.global [%0], [%1], 16;" :: "r"(dst_smem), "l"(src));
}
#define CP_COMMIT() asm volatile("cp.async.commit_group;" ::: "memory")
#define CP_WAIT0()  asm volatile("cp.async.wait_group 0;" ::: "memory")

// ---------------- W prep: coalesced reads, scattered limb writes ----------------
// One thread per W element; idx = k*78+n so consecutive threads read consecutive floats.
__global__ void prep_w(const float* __restrict__ Wm) {
    const int idx = blockIdx.x * blockDim.x + threadIdx.x;
    if (idx >= Dd * Cc) return;
    const int k = idx / Cc, n = idx - k * Cc;
    const float v = Wm[idx];
    const __half h0 = __float2half_rn(v);
    g_Ws[0][n][k] = h0;
    g_Ws[1][n][k] = __float2half_rn(v - __half2float(h0));
}

// ---------------- fused mma GEMM + softmax + argmax + cross-CTA CTC decode ----------------
// CTA tile 128x80, 8 warps as (wm 0..3) x (wn 0..1): warp tile 32x40.
// Per k16-step: 3 limb passes {a0b0, a1b0, a0b1} (a1b1 ~2^-22, dropped).
__global__ __launch_bounds__(256, 2)
void gemm_mma_kernel(const float* __restrict__ feat,
                     const float* __restrict__ bias,
                     float* __restrict__ out, size_t out_elems)
{
    extern __shared__ char dsm[];
    __shared__ float bias_s[80];
    __shared__ float rinv_s[128];

    const int t    = threadIdx.x;
    const int lane = t & 31;
    const int wid  = t >> 5;
    const int wm   = wid & 3;
    const int wn   = wid >> 2;
    const int gID  = lane >> 2;
    const int tid4 = lane & 3;
    const int m0   = blockIdx.x * 128;
    const uint32_t dsmu = (uint32_t)__cvta_generic_to_shared(dsm);

    if (t < 80) bias_s[t] = (t < Cc) ? bias[t] : 0.0f;

    // ldmatrix per-lane address offsets (within plane)
    const uint32_t aoff0 = (uint32_t)((wm * 32 + (lane & 15)) * (AROW * 2) + (lane >> 4) * 16);
    const uint32_t aoff1 = aoff0 + 16 * (AROW * 2);
    const uint32_t boff0 = (uint32_t)((wn * 40 + (lane >> 4) * 8 + (lane & 7)) * (BROW * 2)
                                      + ((lane >> 3) & 1) * 16);
    const uint32_t boff2 = boff0 + 16 * (BROW * 2);
    const uint32_t boff4 = (uint32_t)((wn * 40 + 32 + (lane & 7)) * (BROW * 2)
                                      + ((lane >> 3) & 1) * 16);

    float acc[2][5][4];
#pragma unroll
    for (int i = 0; i < 2; i++)
#pragma unroll
        for (int j = 0; j < 5; j++)
#pragma unroll
            for (int q = 0; q < 4; q++) acc[i][j][q] = 0.0f;

    const float* featb = feat + (size_t)m0 * Dd;

    // ---- A store: split fp32 float4 -> 2 fp16 planes (one STS.64 per plane) ----
    auto storeA = [&](char* aB, int fidx, float4 v) {
        const int r = fidx >> 3, q = fidx & 7;       // 8 float4 per 32-float row
        const int off = r * (AROW * 2) + q * 8;
        uint2 u0, u1;
        split2x2(v.x, v.y, u0.x, u1.x);
        split2x2(v.z, v.w, u0.y, u1.y);
        *(uint2*)(aB + 0 * APL + off) = u0;
        *(uint2*)(aB + 1 * APL + off) = u1;
    };

    // ---- B load: 640 x 16B per chunk via cp.async (2 planes) ----
    auto loadB = [&](uint32_t bBu, int kb) {
#pragma unroll
        for (int i = 0; i < 3; i++) {
            const int idx = t + 256 * i;            // 0..767, use 0..639
            if (idx < 640) {
                const int p = idx / 320, rem = idx - p * 320;
                const int n = rem >> 2, q = rem & 3;
                cp_async16(bBu + p * BPL + n * (BROW * 2) + q * 16,
                           &g_Ws[p][n][kb + q * 8]);
            }
        }
    };

    // ---- prologue: chunk 0 ----
    {
        loadB(dsmu + BOFF, 0);
        CP_COMMIT();
#pragma unroll
        for (int i = 0; i < 4; i++) {
            const int fidx = t + 256 * i;           // 0..1023
            const int r = fidx >> 3, q = fidx & 7;
            float4 v = *reinterpret_cast<const float4*>(featb + (size_t)r * Dd + q * 4);
            storeA(dsm, fidx, v);
        }
        CP_WAIT0();
    }
    __syncthreads();

    // ---- main loop: 16 chunks ----
    for (int ch = 0; ch < NCH; ++ch) {
        const int s = ch & 1;
        const uint32_t aBu = dsmu + s * STAGE;
        const uint32_t bBu = aBu + BOFF;

        float4 pf[4];
        if (ch < NCH - 1) {
            const int kb = (ch + 1) * BK;
#pragma unroll
            for (int i = 0; i < 4; i++) {
                const int fidx = t + 256 * i;
                const int r = fidx >> 3, q = fidx & 7;
                pf[i] = *reinterpret_cast<const float4*>(featb + (size_t)r * Dd + kb + q * 4);
            }
            loadB(dsmu + (s ^ 1) * STAGE + BOFF, kb);
            CP_COMMIT();
        }

        // ---- 2 k-steps of 3-pass fp16 limb mma (ldmatrix fragments) ----
#pragma unroll
        for (int k0 = 0; k0 < 2; k0++) {
            const uint32_t kb2 = k0 * 32;           // 16 fp16 = 32 bytes
            uint32_t afr[2][2][4];
#pragma unroll
            for (int ai = 0; ai < 2; ai++) {
                LDMX4(afr[ai][0], aBu + ai * APL + aoff0 + kb2);
                LDMX4(afr[ai][1], aBu + ai * APL + aoff1 + kb2);
            }
#pragma unroll
            for (int bj = 0; bj < 2; bj++) {
                uint32_t b[5][2];
                LDMX4P(b[0], b[1], bBu + bj * BPL + boff0 + kb2);
                LDMX4P(b[2], b[3], bBu + bj * BPL + boff2 + kb2);
                LDMX2(b[4],        bBu + bj * BPL + boff4 + kb2);
#pragma unroll
                for (int ai = 0; ai <= 1 - bj; ai++)
#pragma unroll
                    for (int i = 0; i < 2; i++)
#pragma unroll
                        for (int j = 0; j < 5; j++)
                            mma16816(acc[i][j], afr[ai][i], b[j]);
            }
        }

        if (ch < NCH - 1) {
            char* aN = dsm + (s ^ 1) * STAGE;
#pragma unroll
            for (int i = 0; i < 4; i++) storeA(aN, t + 256 * i, pf[i]);
            CP_WAIT0();
        }
        __syncthreads();
    }

    // ---- stage logits (+bias) to smem ----
    float* L = (float*)dsm;
#pragma unroll
    for (int i = 0; i < 2; i++)
#pragma unroll
        for (int j = 0; j < 5; j++) {
            const int r0 = wm * 32 + i * 16 + gID;
            const int c0 = wn * 40 + j * 8 + tid4 * 2;
            L[r0 * LP + c0]           = acc[i][j][0] + bias_s[c0];
            L[r0 * LP + c0 + 1]       = acc[i][j][1] + bias_s[c0 + 1];
            L[(r0 + 8) * LP + c0]     = acc[i][j][2] + bias_s[c0];
            L[(r0 + 8) * LP + c0 + 1] = acc[i][j][3] + bias_s[c0 + 1];
        }
    __syncthreads();

    // ---- softmax + argmax: 2 threads per row (39 cols each) ----
    {
        const int r = t >> 1, h = t & 1;
        const int cb = h * 39;
        float mx = -1e30f; int am = 127;
        for (int c = 0; c < 39; c++) {
            float v = L[r * LP + cb + c];
            if (v > mx) { mx = v; am = cb + c; }
        }
        float omx = __shfl_xor_sync(0xFFFFFFFFu, mx, 1);
        int   oam = __shfl_xor_sync(0xFFFFFFFFu, am, 1);
        if (omx > mx || (omx == mx && oam < am)) { mx = omx; am = oam; }
        float ssum = 0.0f;
        for (int c = 0; c < 39; c++) {
            float e = __expf(L[r * LP + cb + c] - mx);
            L[r * LP + cb + c] = e;
            ssum += e;
        }
        ssum += __shfl_xor_sync(0xFFFFFFFFu, ssum, 1);
        if (h == 0) {
            rinv_s[r] = __frcp_rn(ssum);
            g_best[m0 + r] = am;
        }
    }
    __syncthreads();   // all g_best rows of this tile written (CTA-wide)

    // ---- cross-CTA fused CTC decode ----
    // Tile spans <=3 batch elements. Warps 0-2 each claim one candidate batch:
    // add covered-row count to the batch counter; the CTA completing row 80
    // decodes that batch (g_best via L2) and resets the counter for replay.
    if (wid < 3) {
        const int b = m0 / Tlen + wid;
        if (b < Bsz) {
            const int rlo = (b * Tlen > m0) ? b * Tlen : m0;
            const int rhi = (b * Tlen + Tlen < m0 + 128) ? b * Tlen + Tlen : m0 + 128;
            const int nrows = rhi - rlo;
            if (nrows > 0) {
                int doit = 0;
                if (lane == 0) {
                    __threadfence();                      // publish this CTA's g_best rows
                    int old = atomicAdd(&g_cnt[b], nrows);
                    doit = (old + nrows == Tlen);
                }
                doit = __shfl_sync(0xFFFFFFFFu, doit, 0);
                if (doit) {
                    size_t obase = LOGITS_ELEMS + (size_t)b * PRED;
                    if (obase + PRED <= out_elems) {
                        float* lab = out + obase;
                        float buf[1]; (void)buf;
                        if (lane < PRED) lab[lane] = -1.0f;
                        __syncwarp();
                        const int* row = g_best + (size_t)b * Tlen;
                        int prefix = 0, carry = -1;
#pragma unroll
                        for (int seg = 0; seg < 3; seg++) {
                            const int idx = seg * 32 + lane;
                            const bool valid = (idx < Tlen);
                            int v = valid ? __ldcg(row + idx) : BLANKI;
                            int prev = __shfl_up_sync(0xFFFFFFFFu, v, 1);
                            if (lane == 0) prev = carry;
                            const bool keep = valid && (v != BLANKI) && (v != prev);
                            const unsigned mask = __ballot_sync(0xFFFFFFFFu, keep);
                            const int pos = prefix + __popc(mask & ((1u << lane) - 1u));
                            if (keep && pos < PRED) lab[pos] = (float)v;
                            prefix += __popc(mask);
                            carry = __shfl_sync(0xFFFFFFFFu, v, 31);
                        }
                    }
                    if (lane == 0) g_cnt[b] = 0;          // reset for next graph replay
                }
            }
        }
    }

    // ---- coalesced softmax prob writes ----
    for (int idx = t; idx < 128 * Cc; idx += 256) {
        const int r = idx / Cc, c = idx - r * Cc;
        out[(size_t)(m0 + r) * Cc + c] = L[r * LP + c] * rinv_s[r];
    }
}

// ---------------- launch ----------------
extern "C" void kernel_launch(void* const* d_in, const int* in_sizes, int n_in,
                              void* d_out, int out_size)
{
    const float* feat = (const float*)d_in[0];  // [1024,80,512]
    const float* Wm   = (const float*)d_in[1];  // [512,78]
    const float* bias = (const float*)d_in[2];  // [78]
    float* out = (float*)d_out;

    cudaFuncSetAttribute(gemm_mma_kernel,
                         cudaFuncAttributeMaxDynamicSharedMemorySize, SMEM_BYTES);

    prep_w<<<(Dd * Cc + 255) / 256, 256>>>(Wm);
    gemm_mma_kernel<<<Mrows / 128, 256, SMEM_BYTES>>>(feat, bias, out, (size_t)out_size);
}